// round 2
// baseline (speedup 1.0000x reference)
#include <cuda_runtime.h>
#include <math.h>

#define MAXSH 729          // supports nshift_real up to 4
#define MAXN  4096
#define TPB   256

__device__ double g_acc[4];        // 0: pair real, 1: recip, 2: diag(real+self)
__device__ float  g_cf[32];        // constants (see k_setup)
__device__ int    g_ints[4];       // 0: S (real shifts), 1: K (recip pts), 2: nr
__device__ float  g_shifts[MAXSH * 3];
__device__ float  g_shiftnorm[MAXSH];
__device__ float  g_sigma[MAXN];

#define EPS   1e-8f
#define EPS2  1e-16f
#define COEF  14.399645478425668

// ---------------------------------------------------------------- block reduce
__device__ __forceinline__ double block_reduce(double v) {
    __shared__ double s[32];
    #pragma unroll
    for (int o = 16; o; o >>= 1) v += __shfl_down_sync(0xffffffffu, v, o);
    int w = threadIdx.x >> 5, l = threadIdx.x & 31;
    if (l == 0) s[w] = v;
    __syncthreads();
    int nw = (blockDim.x + 31) >> 5;
    v = (threadIdx.x < (unsigned)nw) ? s[threadIdx.x] : 0.0;
    if (w == 0) {
        #pragma unroll
        for (int o = 16; o; o >>= 1) v += __shfl_down_sync(0xffffffffu, v, o);
    }
    return v;
}

// ---------------------------------------------------------------- setup
__global__ void k_setup(const float* __restrict__ cell,
                        const int* __restrict__ nsr,
                        const int* __restrict__ nsk, int N) {
    if (threadIdx.x != 0 || blockIdx.x != 0) return;
    double c[9];
    #pragma unroll
    for (int i = 0; i < 9; i++) c[i] = (double)cell[i];
    double det = c[0]*(c[4]*c[8]-c[5]*c[7])
               - c[1]*(c[3]*c[8]-c[5]*c[6])
               + c[2]*(c[3]*c[7]-c[4]*c[6]);
    double V   = fabs(det);
    double eta = pow(V*V/(double)N, 1.0/6.0) / sqrt(2.0*M_PI);
    double s2l = sqrt(-2.0*log(1e-8));
    double cr  = s2l*eta, ck = s2l/eta;
    double id  = 1.0/det;
    double inv[9];
    inv[0]=(c[4]*c[8]-c[5]*c[7])*id; inv[1]=(c[2]*c[7]-c[1]*c[8])*id; inv[2]=(c[1]*c[5]-c[2]*c[4])*id;
    inv[3]=(c[5]*c[6]-c[3]*c[8])*id; inv[4]=(c[0]*c[8]-c[2]*c[6])*id; inv[5]=(c[2]*c[3]-c[0]*c[5])*id;
    inv[6]=(c[3]*c[7]-c[4]*c[6])*id; inv[7]=(c[1]*c[6]-c[0]*c[7])*id; inv[8]=(c[0]*c[4]-c[1]*c[3])*id;

    g_cf[0] = (float)eta;
    g_cf[1] = (float)(cr*cr);
    g_cf[2] = (float)(ck*ck);
    g_cf[3] = (float)(1.0/(sqrt(2.0)*eta));
    g_cf[4] = (float)V;
    // recip[m][d] = 2*pi * inv(cell)^T [m][d] = 2*pi * inv[d][m]
    for (int m = 0; m < 3; m++)
        for (int d = 0; d < 3; d++)
            g_cf[5 + 3*m + d] = (float)(2.0*M_PI*inv[3*d + m]);
    g_cf[14] = (float)(4.0*M_PI/V);

    int n1 = nsr[0], n2 = nsk[0];
    int d1 = 2*n1 + 1;
    int S  = d1*d1*d1; if (S > MAXSH) S = MAXSH;
    int d2 = 2*n2 + 1;
    g_ints[0] = S;
    g_ints[1] = d2*d2*d2;
    g_ints[2] = n2;
    for (int s = 0; s < S; s++) {
        int a = s/(d1*d1) - n1, b = (s/d1)%d1 - n1, e = s%d1 - n1;
        double sx = a*c[0] + b*c[3] + e*c[6];
        double sy = a*c[1] + b*c[4] + e*c[7];
        double sz = a*c[2] + b*c[5] + e*c[8];
        g_shifts[3*s+0] = (float)sx;
        g_shifts[3*s+1] = (float)sy;
        g_shifts[3*s+2] = (float)sz;
        g_shiftnorm[s]  = (float)sqrt(sx*sx + sy*sy + sz*sz);
    }
    g_acc[0] = g_acc[1] = g_acc[2] = g_acc[3] = 0.0;
}

// ---------------------------------------------------------------- sigma gather
__global__ void k_gather(const float* __restrict__ sigma_table,
                         const int* __restrict__ species, int N) {
    int i = blockIdx.x*blockDim.x + threadIdx.x;
    if (i < N) g_sigma[i] = sigma_table[species[i]];
}

// ---------------------------------------------------------------- real (i<j)
__global__ void __launch_bounds__(TPB)
k_real(const float* __restrict__ pos, const float* __restrict__ q, int N) {
    extern __shared__ float sm[];
    float* sx = sm;          float* sy = sm + N;   float* sz = sm + 2*N;
    float* sq = sm + 3*N;    float* ss = sm + 4*N; float* sh = sm + 5*N;
    int S = g_ints[0];
    for (int i = threadIdx.x; i < N; i += blockDim.x) {
        sx[i] = pos[3*i]; sy[i] = pos[3*i+1]; sz[i] = pos[3*i+2];
        sq[i] = q[i];     ss[i] = g_sigma[i];
    }
    for (int i = threadIdx.x; i < 3*S; i += blockDim.x) sh[i] = g_shifts[i];
    __syncthreads();

    int   b   = blockIdx.x;
    int   i2  = N - 1 - b;
    int   c1  = N - 1 - b;                // cols in row b
    float cr2 = g_cf[1];
    float ce  = g_cf[3];                  // 1/(sqrt2*eta)
    double acc = 0.0;

    for (int w = threadIdx.x; w < N - 1; w += blockDim.x) {
        int i, j;
        if (w < c1) { i = b;  j = b + 1 + w; }
        else        { if (b == i2) continue; i = i2; j = w + 1; }

        float xi = sx[i], yi = sy[i], zi = sz[i];
        float dx0 = sx[j]-xi, dy0 = sy[j]-yi, dz0 = sz[j]-zi;
        float si = ss[i], sj = ss[j];
        float cg = rsqrtf(2.0f*(si*si + sj*sj));   // 1/(sqrt2*gamma)
        float psum = 0.0f;
        for (int s = 0; s < S; s++) {
            float dx = dx0 + sh[3*s], dy = dy0 + sh[3*s+1], dz = dz0 + sh[3*s+2];
            float r2 = dx*dx + dy*dy + dz*dz;
            if (r2 > EPS2 && r2 < cr2) {
                float rinv = rsqrtf(r2);
                float r    = r2 * rinv;
                psum += (erfcf(r*ce) - erfcf(r*cg)) * rinv;
            }
        }
        acc += (double)(psum * sq[i] * sq[j]);
    }
    acc = block_reduce(acc);
    if (threadIdx.x == 0) atomicAdd(&g_acc[0], acc);
}

// ---------------------------------------------------------------- recip |S(k)|^2
__global__ void __launch_bounds__(TPB)
k_recip(const float* __restrict__ pos, const float* __restrict__ q, int N) {
    extern __shared__ float sm[];
    float* sx = sm;       float* sy = sm + N;
    float* sz = sm + 2*N; float* sq = sm + 3*N;
    for (int i = threadIdx.x; i < N; i += blockDim.x) {
        sx[i] = pos[3*i]; sy[i] = pos[3*i+1]; sz[i] = pos[3*i+2];
        sq[i] = q[i];
    }
    __syncthreads();
    int   K   = g_ints[1];
    int   nr  = g_ints[2];
    int   dim = 2*nr + 1;
    float eta = g_cf[0], ck2 = g_cf[2];
    float r00=g_cf[5],r01=g_cf[6],r02=g_cf[7],
          r10=g_cf[8],r11=g_cf[9],r12=g_cf[10],
          r20=g_cf[11],r21=g_cf[12],r22=g_cf[13];
    double acc = 0.0;
    for (int k = blockIdx.x*blockDim.x + threadIdx.x; k < K;
         k += gridDim.x*blockDim.x) {
        int a = k/(dim*dim) - nr, b = (k/dim)%dim - nr, e = k%dim - nr;
        float kx = a*r00 + b*r10 + e*r20;
        float ky = a*r01 + b*r11 + e*r21;
        float kz = a*r02 + b*r12 + e*r22;
        float k2 = kx*kx + ky*ky + kz*kz;
        if (k2 > EPS2 && k2 < ck2) {
            float w = expf(-0.5f*eta*eta*k2) / k2;
            float Sc = 0.0f, Ss = 0.0f;
            for (int i = 0; i < N; i++) {
                float th = kx*sx[i] + ky*sy[i] + kz*sz[i];
                float sn, cs;
                sincosf(th, &sn, &cs);
                Sc += sq[i]*cs;
                Ss += sq[i]*sn;
            }
            acc += (double)(w*(Sc*Sc + Ss*Ss));
        }
    }
    acc = block_reduce(acc);
    if (threadIdx.x == 0) atomicAdd(&g_acc[1], acc);
}

// ---------------------------------------------------------------- diag: real(i==i) + self
__global__ void __launch_bounds__(TPB)
k_diag(const float* __restrict__ q, int N) {
    int i = blockIdx.x*blockDim.x + threadIdx.x;
    double v = 0.0;
    if (i < N) {
        float eta = g_cf[0], ce = g_cf[3], cr2 = g_cf[1];
        int   S   = g_ints[0];
        float sig = g_sigma[i];
        float diag = -sqrtf(2.0f/(float)M_PI)/eta + 1.0f/(sqrtf((float)M_PI)*sig);
        float cg = 1.0f/(2.0f*sig);       // 1/(sqrt2 * sqrt(2)*sigma)
        float ds = 0.0f;
        for (int s = 0; s < S; s++) {
            float rn = g_shiftnorm[s];
            if (rn > EPS && rn*rn < cr2)
                ds += (erfcf(rn*ce) - erfcf(rn*cg)) / rn;
        }
        float qi = q[i];
        v = (double)(qi*qi) * (double)(diag + ds);
    }
    v = block_reduce(v);
    if (threadIdx.x == 0) atomicAdd(&g_acc[2], v);
}

// ---------------------------------------------------------------- assemble
__global__ void k_final(float* out) {
    double c4v = (double)g_cf[14];  // 4*pi/V
    double E = COEF*(g_acc[0] + 0.5*g_acc[2]) + 0.5*COEF*c4v*g_acc[1];
    out[0] = (float)E;
}

// ---------------------------------------------------------------- launch
extern "C" void kernel_launch(void* const* d_in, const int* in_sizes, int n_in,
                              void* d_out, int out_size) {
    const float* pos    = (const float*)d_in[0];
    const float* cell   = (const float*)d_in[1];
    const float* q      = (const float*)d_in[2];
    const float* sigtab = (const float*)d_in[3];
    const int*   spec   = (const int*)d_in[4];
    const int*   nsr    = (const int*)d_in[5];
    const int*   nsk    = (const int*)d_in[6];
    float*       out    = (float*)d_out;

    int N = in_sizes[0] / 3;

    k_setup<<<1, 32>>>(cell, nsr, nsk, N);
    k_gather<<<(N + TPB - 1)/TPB, TPB>>>(sigtab, spec, N);

    int realBlocks = (N + 1) / 2;
    size_t smReal  = (size_t)(5*N + 3*MAXSH) * sizeof(float);
    k_real<<<realBlocks, TPB, smReal>>>(pos, q, N);

    size_t smRecip = (size_t)(4*N) * sizeof(float);
    k_recip<<<64, TPB, smRecip>>>(pos, q, N);

    k_diag<<<(N + TPB - 1)/TPB, TPB>>>(q, N);
    k_final<<<1, 1>>>(out);
}

// round 9
// speedup vs baseline: 1.9980x; 1.9980x over previous
#include <cuda_runtime.h>
#include <math.h>

#define MAXSH 729          // supports nshift_real up to 4
#define MAXN  2048
#define MAXDIM 21          // recip table supports nshift_recip up to 10
#define TPB   256
#define NRC   8            // fast-path nshift_recip
#define DIMC  (2*NRC+1)    // 17

__device__ double g_acc[4];        // 0: pair real, 1: recip, 2: diag(real+self)
__device__ float  g_cf[32];        // constants (see k_setup)
__device__ int    g_ints[4];       // 0: S (real shifts), 1: K (recip pts), 2: nr
__device__ float  g_shifts[MAXSH * 3];
__device__ float  g_shiftnorm[MAXSH];
__device__ float  g_sigma[MAXN];
__device__ float2 g_stepX[MAXN];            // e^{i*phix} per atom
__device__ float2 g_tabY[MAXDIM * MAXN];    // e^{i*(t-nr)*phiy}
__device__ float2 g_tabZ[MAXDIM * MAXN];    // e^{i*(t-nr)*phiz}

#define EPS   1e-8f
#define EPS2  1e-16f
#define COEF  14.399645478425668

// ---------------------------------------------------------------- fast erfc
// Numerical Recipes erfcc: fractional error < 1.2e-7 (x >= 0 here)
__device__ __forceinline__ float erfc_fast(float x) {
    float t = __frcp_rn(fmaf(0.5f, x, 1.0f));
    float p = 0.17087277f;
    p = fmaf(p, t, -0.82215223f);
    p = fmaf(p, t,  1.48851587f);
    p = fmaf(p, t, -1.13520398f);
    p = fmaf(p, t,  0.27886807f);
    p = fmaf(p, t, -0.18628806f);
    p = fmaf(p, t,  0.09678418f);
    p = fmaf(p, t,  0.37409196f);
    p = fmaf(p, t,  1.00002368f);
    float arg = fmaf(-x, x, -1.26551223f) + t * p;
    return t * __expf(arg);
}

// ---------------------------------------------------------------- block reduce
__device__ __forceinline__ double block_reduce(double v) {
    __shared__ double s[32];
    #pragma unroll
    for (int o = 16; o; o >>= 1) v += __shfl_down_sync(0xffffffffu, v, o);
    int w = threadIdx.x >> 5, l = threadIdx.x & 31;
    if (l == 0) s[w] = v;
    __syncthreads();
    int nw = (blockDim.x + 31) >> 5;
    v = (threadIdx.x < (unsigned)nw) ? s[threadIdx.x] : 0.0;
    if (w == 0) {
        #pragma unroll
        for (int o = 16; o; o >>= 1) v += __shfl_down_sync(0xffffffffu, v, o);
    }
    return v;
}

// ---------------------------------------------------------------- setup
__global__ void k_setup(const float* __restrict__ cell,
                        const int* __restrict__ nsr,
                        const int* __restrict__ nsk, int N) {
    if (threadIdx.x != 0 || blockIdx.x != 0) return;
    double c[9];
    #pragma unroll
    for (int i = 0; i < 9; i++) c[i] = (double)cell[i];
    double det = c[0]*(c[4]*c[8]-c[5]*c[7])
               - c[1]*(c[3]*c[8]-c[5]*c[6])
               + c[2]*(c[3]*c[7]-c[4]*c[6]);
    double V   = fabs(det);
    double eta = pow(V*V/(double)N, 1.0/6.0) / sqrt(2.0*M_PI);
    double s2l = sqrt(-2.0*log(1e-8));
    double cr  = s2l*eta, ck = s2l/eta;
    double id  = 1.0/det;
    double inv[9];
    inv[0]=(c[4]*c[8]-c[5]*c[7])*id; inv[1]=(c[2]*c[7]-c[1]*c[8])*id; inv[2]=(c[1]*c[5]-c[2]*c[4])*id;
    inv[3]=(c[5]*c[6]-c[3]*c[8])*id; inv[4]=(c[0]*c[8]-c[2]*c[6])*id; inv[5]=(c[2]*c[3]-c[0]*c[5])*id;
    inv[6]=(c[3]*c[7]-c[4]*c[6])*id; inv[7]=(c[1]*c[6]-c[0]*c[7])*id; inv[8]=(c[0]*c[4]-c[1]*c[3])*id;

    g_cf[0] = (float)eta;
    g_cf[1] = (float)(cr*cr);
    g_cf[2] = (float)(ck*ck);
    g_cf[3] = (float)(1.0/(sqrt(2.0)*eta));
    g_cf[4] = (float)V;
    // recip[m][d] = 2*pi * inv(cell)^T [m][d] = 2*pi * inv[d][m]
    for (int m = 0; m < 3; m++)
        for (int d = 0; d < 3; d++)
            g_cf[5 + 3*m + d] = (float)(2.0*M_PI*inv[3*d + m]);
    g_cf[14] = (float)(4.0*M_PI/V);

    int n1 = nsr[0], n2 = nsk[0];
    int d1 = 2*n1 + 1;
    int S  = d1*d1*d1; if (S > MAXSH) S = MAXSH;
    int d2 = 2*n2 + 1;
    g_ints[0] = S;
    g_ints[1] = d2*d2*d2;
    g_ints[2] = n2;
    for (int s = 0; s < S; s++) {
        int a = s/(d1*d1) - n1, b = (s/d1)%d1 - n1, e = s%d1 - n1;
        double sx = a*c[0] + b*c[3] + e*c[6];
        double sy = a*c[1] + b*c[4] + e*c[7];
        double sz = a*c[2] + b*c[5] + e*c[8];
        g_shifts[3*s+0] = (float)sx;
        g_shifts[3*s+1] = (float)sy;
        g_shifts[3*s+2] = (float)sz;
        g_shiftnorm[s]  = (float)sqrt(sx*sx + sy*sy + sz*sz);
    }
    g_acc[0] = g_acc[1] = g_acc[2] = g_acc[3] = 0.0;
}

// ---------------------------------------------------------------- per-atom precompute
// sigma gather + phase tables for the factorized recip kernel
__global__ void k_phase(const float* __restrict__ pos,
                        const float* __restrict__ sigma_table,
                        const int* __restrict__ species, int N) {
    int i = blockIdx.x*blockDim.x + threadIdx.x;
    if (i >= N) return;
    g_sigma[i] = sigma_table[species[i]];

    float px = pos[3*i], py = pos[3*i+1], pz = pos[3*i+2];
    float p0 = g_cf[5]*px  + g_cf[6]*py  + g_cf[7]*pz;   // R0 . p
    float p1 = g_cf[8]*px  + g_cf[9]*py  + g_cf[10]*pz;  // R1 . p
    float p2 = g_cf[11]*px + g_cf[12]*py + g_cf[13]*pz;  // R2 . p
    float sn, cs;
    sincosf(p0, &sn, &cs);
    g_stepX[i] = make_float2(cs, sn);
    int nr = g_ints[2];
    int dim = 2*nr + 1;
    if (dim > MAXDIM) return;
    for (int t = 0; t < dim; t++) {
        float m = (float)(t - nr);
        sincosf(m*p1, &sn, &cs);
        g_tabY[t*MAXN + i] = make_float2(cs, sn);
        sincosf(m*p2, &sn, &cs);
        g_tabZ[t*MAXN + i] = make_float2(cs, sn);
    }
}

// ---------------------------------------------------------------- real (i<j)
__global__ void __launch_bounds__(TPB)
k_real(const float* __restrict__ pos, const float* __restrict__ q, int N) {
    extern __shared__ float sm[];
    float* sx = sm;          float* sy = sm + N;   float* sz = sm + 2*N;
    float* sq = sm + 3*N;    float* ss = sm + 4*N; float* sh = sm + 5*N;
    int S = g_ints[0];
    for (int i = threadIdx.x; i < N; i += blockDim.x) {
        sx[i] = pos[3*i]; sy[i] = pos[3*i+1]; sz[i] = pos[3*i+2];
        sq[i] = q[i];     ss[i] = g_sigma[i];
    }
    for (int i = threadIdx.x; i < 3*S; i += blockDim.x) sh[i] = g_shifts[i];
    __syncthreads();

    int   b   = blockIdx.x;
    int   i2  = N - 1 - b;
    int   c1  = N - 1 - b;                // cols in row b
    float cr2 = g_cf[1];
    float ce  = g_cf[3];                  // 1/(sqrt2*eta)
    double acc = 0.0;

    for (int w = threadIdx.x + blockIdx.y*blockDim.x; w < N - 1;
         w += blockDim.x*gridDim.y) {
        int i, j;
        if (w < c1) { i = b;  j = b + 1 + w; }
        else        { if (b == i2) continue; i = i2; j = w + 1; }

        float dx0 = sx[j]-sx[i], dy0 = sy[j]-sy[i], dz0 = sz[j]-sz[i];
        float si = ss[i], sj = ss[j];
        float cg = rsqrtf(2.0f*(si*si + sj*sj));   // 1/(sqrt2*gamma)
        float psum = 0.0f;
        for (int s = 0; s < S; s++) {
            float dx = dx0 + sh[3*s], dy = dy0 + sh[3*s+1], dz = dz0 + sh[3*s+2];
            float r2 = fmaf(dx,dx, fmaf(dy,dy, dz*dz));
            if (r2 > EPS2 && r2 < cr2) {
                float rinv = rsqrtf(r2);
                float r    = r2 * rinv;
                psum += (erfc_fast(r*ce) - erfc_fast(r*cg)) * rinv;
            }
        }
        acc += (double)(psum * sq[i] * sq[j]);
    }
    acc = block_reduce(acc);
    if (threadIdx.x == 0) atomicAdd(&g_acc[0], acc);
}

// ---------------------------------------------------------------- recip fast path (nr == 8)
// One block per (b,e) pair; phase recurrence over a; |S(k)|^2 accumulation.
__global__ void __launch_bounds__(TPB)
k_recip17(const float* __restrict__ q, int N) {
    if (g_ints[2] != NRC) return;
    int bi = blockIdx.x;
    int b  = bi / DIMC, e = bi % DIMC;

    float aC[DIMC], aS[DIMC];
    #pragma unroll
    for (int A = 0; A < DIMC; A++) { aC[A] = 0.0f; aS[A] = 0.0f; }

    const float2* tY = g_tabY + b*MAXN;
    const float2* tZ = g_tabZ + e*MAXN;

    for (int i = threadIdx.x; i < N; i += blockDim.x) {
        float2 Y  = tY[i];
        float2 Z  = tZ[i];
        float2 st = g_stepX[i];
        float qi  = q[i];
        float br = qi*(Y.x*Z.x - Y.y*Z.y);
        float bs = qi*(Y.x*Z.y + Y.y*Z.x);
        aC[NRC] += br; aS[NRC] += bs;
        float cr = br, ci = bs;
        #pragma unroll
        for (int t = 1; t <= NRC; t++) {
            float nr_ = cr*st.x - ci*st.y;
            float ni_ = cr*st.y + ci*st.x;
            cr = nr_; ci = ni_;
            aC[NRC+t] += cr; aS[NRC+t] += ci;
        }
        cr = br; ci = bs;
        #pragma unroll
        for (int t = 1; t <= NRC; t++) {
            float nr_ =  cr*st.x + ci*st.y;
            float ni_ = -cr*st.y + ci*st.x;
            cr = nr_; ci = ni_;
            aC[NRC-t] += cr; aS[NRC-t] += ci;
        }
    }

    // warp reduce each accumulator
    #pragma unroll
    for (int A = 0; A < DIMC; A++) {
        #pragma unroll
        for (int o = 16; o; o >>= 1) {
            aC[A] += __shfl_down_sync(0xffffffffu, aC[A], o);
            aS[A] += __shfl_down_sync(0xffffffffu, aS[A], o);
        }
    }
    __shared__ float2 red[TPB/32][DIMC];
    __shared__ double fin[DIMC];
    int w = threadIdx.x >> 5, l = threadIdx.x & 31;
    if (l == 0) {
        #pragma unroll
        for (int A = 0; A < DIMC; A++) red[w][A] = make_float2(aC[A], aS[A]);
    }
    __syncthreads();
    if (threadIdx.x < DIMC) {
        int A = threadIdx.x;
        float Sc = 0.0f, Ss = 0.0f;
        int nw = blockDim.x >> 5;
        for (int w2 = 0; w2 < nw; w2++) { Sc += red[w2][A].x; Ss += red[w2][A].y; }
        int ia = A - NRC, ib = b - NRC, ie = e - NRC;
        float kx = ia*g_cf[5]  + ib*g_cf[8]  + ie*g_cf[11];
        float ky = ia*g_cf[6]  + ib*g_cf[9]  + ie*g_cf[12];
        float kz = ia*g_cf[7]  + ib*g_cf[10] + ie*g_cf[13];
        float k2 = kx*kx + ky*ky + kz*kz;
        double v = 0.0;
        float eta = g_cf[0], ck2 = g_cf[2];
        if (k2 > EPS2 && k2 < ck2) {
            float wgt = __expf(-0.5f*eta*eta*k2) / k2;
            v = (double)(wgt*(Sc*Sc + Ss*Ss));
        }
        fin[A] = v;
    }
    __syncthreads();
    if (threadIdx.x == 0) {
        double s = 0.0;
        for (int A = 0; A < DIMC; A++) s += fin[A];
        atomicAdd(&g_acc[1], s);
    }
}

// ---------------------------------------------------------------- recip generic fallback
__global__ void __launch_bounds__(TPB)
k_recip_gen(const float* __restrict__ pos, const float* __restrict__ q, int N) {
    if (g_ints[2] == NRC) return;
    extern __shared__ float sm[];
    float* sx = sm;       float* sy = sm + N;
    float* sz = sm + 2*N; float* sq = sm + 3*N;
    for (int i = threadIdx.x; i < N; i += blockDim.x) {
        sx[i] = pos[3*i]; sy[i] = pos[3*i+1]; sz[i] = pos[3*i+2];
        sq[i] = q[i];
    }
    __syncthreads();
    int   K   = g_ints[1];
    int   nr  = g_ints[2];
    int   dim = 2*nr + 1;
    float eta = g_cf[0], ck2 = g_cf[2];
    float r00=g_cf[5],r01=g_cf[6],r02=g_cf[7],
          r10=g_cf[8],r11=g_cf[9],r12=g_cf[10],
          r20=g_cf[11],r21=g_cf[12],r22=g_cf[13];
    double acc = 0.0;
    for (int k = blockIdx.x*blockDim.x + threadIdx.x; k < K;
         k += gridDim.x*blockDim.x) {
        int a = k/(dim*dim) - nr, b = (k/dim)%dim - nr, e = k%dim - nr;
        float kx = a*r00 + b*r10 + e*r20;
        float ky = a*r01 + b*r11 + e*r21;
        float kz = a*r02 + b*r12 + e*r22;
        float k2 = kx*kx + ky*ky + kz*kz;
        if (k2 > EPS2 && k2 < ck2) {
            float w = expf(-0.5f*eta*eta*k2) / k2;
            float Sc = 0.0f, Ss = 0.0f;
            for (int i = 0; i < N; i++) {
                float th = kx*sx[i] + ky*sy[i] + kz*sz[i];
                float sn, cs;
                sincosf(th, &sn, &cs);
                Sc += sq[i]*cs;
                Ss += sq[i]*sn;
            }
            acc += (double)(w*(Sc*Sc + Ss*Ss));
        }
    }
    acc = block_reduce(acc);
    if (threadIdx.x == 0) atomicAdd(&g_acc[1], acc);
}

// ---------------------------------------------------------------- diag: real(i==i) + self
__global__ void __launch_bounds__(TPB)
k_diag(const float* __restrict__ q, int N) {
    int i = blockIdx.x*blockDim.x + threadIdx.x;
    double v = 0.0;
    if (i < N) {
        float eta = g_cf[0], ce = g_cf[3], cr2 = g_cf[1];
        int   S   = g_ints[0];
        float sig = g_sigma[i];
        float diag = -sqrtf(2.0f/(float)M_PI)/eta + 1.0f/(sqrtf((float)M_PI)*sig);
        float cg = 1.0f/(2.0f*sig);       // 1/(sqrt2 * sqrt(2)*sigma)
        float ds = 0.0f;
        for (int s = 0; s < S; s++) {
            float rn = g_shiftnorm[s];
            if (rn > EPS && rn*rn < cr2)
                ds += (erfcf(rn*ce) - erfcf(rn*cg)) / rn;
        }
        float qi = q[i];
        v = (double)(qi*qi) * (double)(diag + ds);
    }
    v = block_reduce(v);
    if (threadIdx.x == 0) atomicAdd(&g_acc[2], v);
}

// ---------------------------------------------------------------- assemble
__global__ void k_final(float* out) {
    double c4v = (double)g_cf[14];  // 4*pi/V
    double E = COEF*(g_acc[0] + 0.5*g_acc[2]) + 0.5*COEF*c4v*g_acc[1];
    out[0] = (float)E;
}

// ---------------------------------------------------------------- launch
extern "C" void kernel_launch(void* const* d_in, const int* in_sizes, int n_in,
                              void* d_out, int out_size) {
    const float* pos    = (const float*)d_in[0];
    const float* cell   = (const float*)d_in[1];
    const float* q      = (const float*)d_in[2];
    const float* sigtab = (const float*)d_in[3];
    const int*   spec   = (const int*)d_in[4];
    const int*   nsr    = (const int*)d_in[5];
    const int*   nsk    = (const int*)d_in[6];
    float*       out    = (float*)d_out;

    int N = in_sizes[0] / 3;

    k_setup<<<1, 32>>>(cell, nsr, nsk, N);
    k_phase<<<(N + TPB - 1)/TPB, TPB>>>(pos, sigtab, spec, N);

    dim3 gReal((N + 1)/2, 2);
    size_t smReal = (size_t)(5*N + 3*MAXSH) * sizeof(float);
    k_real<<<gReal, TPB, smReal>>>(pos, q, N);

    k_recip17<<<DIMC*DIMC, TPB>>>(q, N);
    size_t smRecip = (size_t)(4*N) * sizeof(float);
    k_recip_gen<<<64, TPB, smRecip>>>(pos, q, N);

    k_diag<<<(N + TPB - 1)/TPB, TPB>>>(q, N);
    k_final<<<1, 1>>>(out);
}